// round 16
// baseline (speedup 1.0000x reference)
#include <cuda_runtime.h>
#include <cuda_fp16.h>
#include <cstdint>

constexpr int NROWS  = 65536;
constexpr int DFEAT  = 32;
constexpr int H      = 128;
constexpr int NJ     = H + 1;          // 129 intervals
constexpr int SPLITS = 64;
constexpr int RPB    = NROWS / SPLITS; // 1024 rows per main CTA
constexpr int KCH    = 16;             // k-chunks per CTA (half of 32)
constexpr int SLOTS  = 136;            // padded slot stride (132 used)

// persistent scratch (static device globals — no runtime allocation)
__device__ uint4  g_tab4[DFEAT][NJ][32];  // w3-folded, sign-sorted chunks
__device__ uint4  g_ext [DFEAT][NJ];      // 33rd chunk (pure-neg overflow)
__device__ float2 g_aff [DFEAT][NJ];      // (Sp, Sq): sum of neg-side z~
__device__ float  g_kn  [DFEAT][H];       // sorted knees
__device__ int    g_cb  [DFEAT];          // first neg chunk index

__device__ __forceinline__ uint32_t h2u(__half2 h) {
    return *reinterpret_cast<uint32_t*>(&h);
}
__device__ __forceinline__ __half2 u2h(uint32_t u) {
    return *reinterpret_cast<__half2*>(&u);
}

// ---------------- precompute ----------------
// SMEM float offsets
constexpr int O_W2  = 0;                 // W2slot [128][SLOTS]
constexpr int O_B2S = O_W2 + 128 * SLOTS;   // 17408
constexpr int O_W1  = O_B2S + SLOTS;     // b2slot then arrays
constexpr int O_B1  = O_W1 + H;
constexpr int O_W3  = O_B1 + H;
constexpr int O_KNS = O_W3 + H;
constexpr int O_SUS = O_KNS + H;
constexpr int O_SVS = O_SUS + H;
constexpr int O_CIX = O_SVS + H;         // int[128]
constexpr int O_SLK = O_CIX + H;         // int[SLOTS]
constexpr int O_TC  = O_SLK + SLOTS;     // float[128]
constexpr int O_MSC = O_TC + H;          // misc
constexpr int PRE_FLOATS = O_MSC + 8;
constexpr int PRE_SMEM = PRE_FLOATS * 4;

__global__ void __launch_bounds__(128)
kan_precompute(const float* __restrict__ W1, const float* __restrict__ b1,
               const float* __restrict__ W2, const float* __restrict__ b2,
               const float* __restrict__ W3)
{
    extern __shared__ float ps[];
    float* W2s = ps + O_W2;
    float* b2s = ps + O_B2S;
    float* w1s = ps + O_W1;
    float* b1s = ps + O_B1;
    float* w3s = ps + O_W3;
    float* kns = ps + O_KNS;
    float* sus = ps + O_SUS;
    float* svs = ps + O_SVS;
    int*   cix = reinterpret_cast<int*>(ps + O_CIX);
    int*   slk = reinterpret_cast<int*>(ps + O_SLK);
    float* Tc  = ps + O_TC;
    float* msc = ps + O_MSC;

    const int d = blockIdx.x, tid = threadIdx.x;

    w1s[tid] = W1[d * H + tid];
    b1s[tid] = b1[d * H + tid];
    w3s[tid] = W3[d * H + tid];
    for (int s = tid; s < SLOTS; s += 128) slk[s] = -1;
    __syncthreads();

    // sign-sorted slot assignment (k = tid)
    int npos = 0, posrank = 0, negrank = 0;
    for (int k = 0; k < H; ++k) {
        const bool p = (w3s[k] > 0.f);
        npos += p;
        if (k < tid) { posrank += p; negrank += !p; }
    }
    const int cb = (npos + 3) >> 2;                 // first neg chunk
    const int myslot = (w3s[tid] > 0.f) ? posrank : 4 * cb + negrank;
    slk[myslot] = tid;
    __syncthreads();

    // W2slot[c][s] = W2[c][k(s)] * w3[k(s)]  (0 for pads); b2slot likewise
    {
        const float* w2d = W2 + (size_t)d * H * H;
        const int c = tid;
        for (int s = 0; s < SLOTS; ++s) {
            const int k = slk[s];
            W2s[c * SLOTS + s] = (k >= 0) ? w2d[c * H + k] * w3s[k] : 0.f;
        }
        for (int s = tid; s < SLOTS; s += 128) {
            const int k = slk[s];
            b2s[s] = (k >= 0) ? b2[d * H + k] * w3s[k] : 0.f;
        }
    }

    // knee + exact rank sort (thread = unit)
    {
        const float w = w1s[tid], bb = b1s[tid];
        const float t = (w != 0.f) ? (-bb / w) : 3.0e38f;
        int rank = 0;
        for (int c = 0; c < H; ++c) {
            const float wc = w1s[c], bc = b1s[c];
            const float tc = (wc != 0.f) ? (-bc / wc) : 3.0e38f;
            rank += (tc < t) || ((tc == t) && (c < tid));
        }
        kns[rank] = t;
        cix[rank] = tid;
        sus[rank] = fabsf(w);
        svs[rank] = (w > 0.f) ? bb : -bb;
    }
    __syncthreads();
    g_kn[d][tid] = kns[tid];

    // Tc[c] = sum of neg-side W2slot row; B0 = sum of neg-side b2slot
    {
        const int c = tid;
        float t = 0.f;
        for (int s = 4 * cb; s < SLOTS; ++s) t += W2s[c * SLOTS + s];
        Tc[c] = t;
        if (tid == 0) {
            float b0 = 0.f;
            for (int s = 4 * cb; s < SLOTS; ++s) b0 += b2s[s];
            msc[0] = b0;
        }
        if (tid == 0) g_cb[d] = cb;
    }
    __syncthreads();
    const float B0 = msc[0];

    // incremental build of 32 main chunks (slots 0..127)
    {
        const int warp = tid >> 5, lane = tid & 31;
        const int j0   = (warp == 0) ? 0 : warp * 32 + 1;
        const int jend = warp * 32 + 32;
        const int kb   = lane * 4;

        float m;
        if (j0 == 0) m = kns[0] - 1.0f;
        else         m = kns[j0 - 1] + 0.5f * (kns[j0] - kns[j0 - 1]);

        float P[4] = {0.f, 0.f, 0.f, 0.f};
        float Q[4] = {b2s[kb], b2s[kb + 1], b2s[kb + 2], b2s[kb + 3]};
        for (int c = 0; c < H; ++c) {
            const float wc = w1s[c], bc = b1s[c];
            if (m * wc + bc > 0.f) {
                const float4 wv =
                    *reinterpret_cast<const float4*>(W2s + c * SLOTS + kb);
                P[0] = fmaf(wc, wv.x, P[0]); Q[0] = fmaf(bc, wv.x, Q[0]);
                P[1] = fmaf(wc, wv.y, P[1]); Q[1] = fmaf(bc, wv.y, Q[1]);
                P[2] = fmaf(wc, wv.z, P[2]); Q[2] = fmaf(bc, wv.z, Q[2]);
                P[3] = fmaf(wc, wv.w, P[3]); Q[3] = fmaf(bc, wv.w, Q[3]);
            }
        }
        auto store = [&](int j) {
            uint4 u;
            u.x = h2u(__floats2half2_rn(P[0], P[1]));
            u.y = h2u(__floats2half2_rn(P[2], P[3]));
            u.z = h2u(__floats2half2_rn(Q[0], Q[1]));
            u.w = h2u(__floats2half2_rn(Q[2], Q[3]));
            g_tab4[d][j][lane] = u;
        };
        store(j0);
        for (int j = j0 + 1; j <= jend; ++j) {
            const int   c  = cix[j - 1];
            const float uu = sus[j - 1], vv = svs[j - 1];
            const float4 wv =
                *reinterpret_cast<const float4*>(W2s + c * SLOTS + kb);
            P[0] = fmaf(uu, wv.x, P[0]); Q[0] = fmaf(vv, wv.x, Q[0]);
            P[1] = fmaf(uu, wv.y, P[1]); Q[1] = fmaf(vv, wv.y, Q[1]);
            P[2] = fmaf(uu, wv.z, P[2]); Q[2] = fmaf(vv, wv.z, Q[2]);
            P[3] = fmaf(uu, wv.w, P[3]); Q[3] = fmaf(vv, wv.w, Q[3]);
            store(j);
        }
    }
    __syncthreads();

    // direct eval: extra chunk (slots 128..131) + affine (Sp, Sq) per j
    for (int j = tid; j < NJ; j += 128) {
        float m;
        if (j == 0)      m = kns[0] - 1.0f;
        else if (j == H) m = kns[H - 1] + 1.0f;
        else             m = kns[j - 1] + 0.5f * (kns[j] - kns[j - 1]);

        float Sp = 0.f, Sq = 0.f;
        float eP[4] = {0.f, 0.f, 0.f, 0.f};
        float eQ[4] = {b2s[128], b2s[129], b2s[130], b2s[131]};
        for (int c = 0; c < H; ++c) {
            const float wc = w1s[c], bc = b1s[c];
            if (m * wc + bc > 0.f) {
                const float tc = Tc[c];
                Sp = fmaf(wc, tc, Sp);
                Sq = fmaf(bc, tc, Sq);
                const float4 wv =
                    *reinterpret_cast<const float4*>(W2s + c * SLOTS + 128);
                eP[0] = fmaf(wc, wv.x, eP[0]); eQ[0] = fmaf(bc, wv.x, eQ[0]);
                eP[1] = fmaf(wc, wv.y, eP[1]); eQ[1] = fmaf(bc, wv.y, eQ[1]);
                eP[2] = fmaf(wc, wv.z, eP[2]); eQ[2] = fmaf(bc, wv.z, eQ[2]);
                eP[3] = fmaf(wc, wv.w, eP[3]); eQ[3] = fmaf(bc, wv.w, eQ[3]);
            }
        }
        g_aff[d][j] = make_float2(Sp, Sq + B0);
        uint4 u;
        u.x = h2u(__floats2half2_rn(eP[0], eP[1]));
        u.y = h2u(__floats2half2_rn(eP[2], eP[3]));
        u.z = h2u(__floats2half2_rn(eQ[0], eQ[1]));
        u.w = h2u(__floats2half2_rn(eQ[2], eQ[3]));
        g_ext[d][j] = u;
    }
}

// ---------------- main: w3-folded table, signed chunk accumulate ----------
constexpr int MS_TAB    = 0;                      // NJ*16 uint4 = 8256 u32
constexpr int MS_KN     = NJ * KCH * 4;           // 8256
constexpr int MS_EXT    = MS_KN + H;              // 8384 (uint4[NJ] = 516 u32)
constexpr int MS_AFF    = MS_EXT + NJ * 4 + 4;    // 8904 (float2[NJ])
constexpr int MS_FLOATS = MS_AFF + NJ * 2 + 2;    // 9164
constexpr int MAIN_SMEM = MS_FLOATS * 4;          // 36656 B (x4 = 146.6 KB)

__global__ void __launch_bounds__(256, 4)
kan_main(const float* __restrict__ x, const float* __restrict__ b3,
         float* __restrict__ out)
{
    extern __shared__ float s[];
    uint4*  tab = reinterpret_cast<uint4*>(s);
    float*  kns = s + MS_KN;
    uint4*  ext = reinterpret_cast<uint4*>(s + MS_EXT);
    float2* aff = reinterpret_cast<float2*>(s + MS_AFF);

    const int tid   = threadIdx.x;
    const int d     = blockIdx.x & (DFEAT - 1);   // d fastest -> x L2 reuse
    const int kh    = (blockIdx.x >> 5) & 1;      // k-half
    const int split = blockIdx.x >> 6;
    const int n0    = split * RPB;
    const int lane  = tid & 31, w = tid >> 5;

    // prologue
    {
        for (int i = tid; i < NJ * KCH; i += 256) {
            const int j = i >> 4, c = i & (KCH - 1);
            tab[i] = g_tab4[d][j][kh * KCH + c];
        }
        for (int i = tid; i < H; i += 256) kns[i] = g_kn[d][i];
        if (kh) { for (int i = tid; i < NJ; i += 256) ext[i] = g_ext[d][i]; }
        else    { for (int i = tid; i < NJ; i += 256) aff[i] = g_aff[d][i]; }
    }
    const int   cb  = __ldg(&g_cb[d]);
    const float b3d = (kh == 0) ? __ldg(&b3[d]) : 0.f;
    __syncthreads();

    const __half2 zero2 = __float2half2_rn(0.f);

    for (int b = 0; b < RPB / 256; ++b) {     // 4 batches; lane owns a row
        const int row = n0 + (b * 8 + w) * 32 + lane;
        const float xv = x[(size_t)row * DFEAT + d];

        // locate interval (binary count over sorted knees)
        int j = 0;
        #pragma unroll
        for (int stp = 128; stp > 0; stp >>= 1)
            if (j + stp <= H && kns[j + stp - 1] <= xv) j += stp;

        const __half2 x2 = __half2half2(__float2half_rn(xv));
        const int base = j * KCH;

        float acc = 0.f;
        #pragma unroll
        for (int i = 0; i < KCH; ++i) {
            const int c  = (i + lane) & (KCH - 1);  // rotation: conflict-free
            const int gc = kh * KCH + c;            // global chunk index
            const uint4 pv = tab[base + c];
            const __half2 u01 = __hmax2(__hfma2(x2, u2h(pv.x), u2h(pv.z)), zero2);
            const __half2 u23 = __hmax2(__hfma2(x2, u2h(pv.y), u2h(pv.w)), zero2);
            const float2 pf = __half22float2(__hadd2(u01, u23));
            const float  sv = pf.x + pf.y;
            acc += (gc < cb) ? sv : -sv;            // pos chunks +, neg -
        }

        if (kh) {
            // extra (pure-neg) chunk
            const uint4 ev = ext[j];
            const __half2 u01 = __hmax2(__hfma2(x2, u2h(ev.x), u2h(ev.z)), zero2);
            const __half2 u23 = __hmax2(__hfma2(x2, u2h(ev.y), u2h(ev.w)), zero2);
            const float2 pf = __half22float2(__hadd2(u01, u23));
            acc -= (pf.x + pf.y);
        } else {
            // affine neg-side term + b3
            const float2 a = aff[j];
            acc += fmaf(xv, a.x, a.y) + b3d;
        }
        atomicAdd(out + row, acc);
    }
}

extern "C" void kernel_launch(void* const* d_in, const int* in_sizes, int n_in,
                              void* d_out, int out_size) {
    const float* x  = (const float*)d_in[0];
    const float* W1 = (const float*)d_in[1];
    const float* b1 = (const float*)d_in[2];
    const float* W2 = (const float*)d_in[3];
    const float* b2 = (const float*)d_in[4];
    const float* W3 = (const float*)d_in[5];
    const float* b3 = (const float*)d_in[6];
    float* out = (float*)d_out;

    cudaFuncSetAttribute(kan_precompute,
                         cudaFuncAttributeMaxDynamicSharedMemorySize, PRE_SMEM);
    cudaFuncSetAttribute(kan_main,
                         cudaFuncAttributeMaxDynamicSharedMemorySize, MAIN_SMEM);

    cudaMemsetAsync(d_out, 0, (size_t)out_size * sizeof(float), 0);
    kan_precompute<<<DFEAT, 128, PRE_SMEM>>>(W1, b1, W2, b2, W3);
    kan_main<<<DFEAT * 2 * SPLITS, 256, MAIN_SMEM>>>(x, b3, out);
}